// round 1
// baseline (speedup 1.0000x reference)
#include <cuda_runtime.h>
#include <math.h>

#define NSTEPS 8760
#define NGRID  2048
#define NMUL   2
#define LENF   72
#define DTC    (1.0f/24.0f)

// Scratch (device globals: no allocation allowed in kernel_launch)
__device__ float g_q[NSTEPS * NGRID];     // mean discharge per (t, grid)
__device__ float g_w[LENF * NGRID];       // normalized gamma weights, [k][g] layout

// ---------------------------------------------------------------------------
// Stage 1: HBV scan. One thread per (grid, mul). 4096 threads total.
// Latency-bound by design; forcing loads software-pipelined U=8 steps ahead.
// ---------------------------------------------------------------------------
__global__ void __launch_bounds__(128) hbv_scan_kernel(
    const float* __restrict__ prcp,
    const float* __restrict__ tmean,
    const float* __restrict__ pet,
    const float* __restrict__ phy)
{
    const int tid = blockIdx.x * 128 + threadIdx.x;   // 0..4095
    const int g = tid >> 1;
    const int m = tid & 1;

    // BOUNDS baked as immediates (fully unrolled)
    const float lb[19] = {1.0f, 50.0f, 0.05f, 0.01f, 0.001f, 0.2f, 0.0f, 0.0f,
                          -2.5f, 0.5f, 0.0f, 0.0f, 0.3f, 0.0f, 0.0f, 0.0f,
                          5.0f/DTC, 0.0f, 0.5f};
    const float ub[19] = {6.0f, 1000.0f, 0.9f, 0.5f, 0.2f, 1.0f, 10.0f, 100.0f,
                          2.5f, 10.0f, 0.1f, 0.2f, 5.0f, 1.0f, 20.0f, 2500.0f,
                          120.0f/DTC, 1.0f, 5.0f};
    float pp[19];
#pragma unroll
    for (int i = 0; i < 19; i++) {
        float r = phy[g * (19 * NMUL) + i * NMUL + m];
        pp[i] = lb[i] + r * (ub[i] - lb[i]);
    }
    const float BETA   = pp[0];
    const float FC     = pp[1];
    const float LP     = pp[5];
    const float UZL    = pp[7];
    const float TTp    = pp[8];
    const float CWH    = pp[11];
    const float BETAET = pp[12];
    const float Cc     = pp[13];
    const float FMIN   = pp[17];
    const float ALPHA  = pp[18];

    const float invFC      = 1.0f / FC;
    const float k0dt       = pp[2] * DTC;
    const float k1dt       = pp[3] * DTC;
    const float k2dt       = pp[4] * DTC;
    const float percdt     = pp[6] * DTC;
    const float cfmaxdt    = pp[9] * DTC;
    const float cfrcfmaxdt = pp[10] * cfmaxdt;
    const float f0dt       = pp[16] * DTC;
    const float invLPFC    = 1.0f / (LP * FC);
    const float om_fmin    = 1.0f - FMIN;

    float SP  = 0.001f, MW = 0.001f, SM = 0.001f, SUZ = 0.001f, SLZ = 0.001f;

    const int U = 8;                     // 8760 % 8 == 0
    float Pb[U], Tb[U], Eb[U];
#pragma unroll
    for (int u = 0; u < U; u++) {
        Pb[u] = prcp [u * NGRID + g];
        Tb[u] = tmean[u * NGRID + g];
        Eb[u] = pet  [u * NGRID + g];
    }

    for (int t0 = 0; t0 < NSTEPS; t0 += U) {
        float Pn[U], Tn[U], En[U];
        const int t1 = t0 + U;
        if (t1 < NSTEPS) {
#pragma unroll
            for (int u = 0; u < U; u++) {
                Pn[u] = prcp [(t1 + u) * NGRID + g];
                Tn[u] = tmean[(t1 + u) * NGRID + g];
                En[u] = pet  [(t1 + u) * NGRID + g];
            }
        }
#pragma unroll
        for (int u = 0; u < U; u++) {
            const float P  = Pb[u];
            const float T  = Tb[u];
            const float PV = Eb[u];

            float RAIN, SNOW;
            if (T >= TTp) { RAIN = P;    SNOW = 0.0f; }
            else          { RAIN = 0.0f; SNOW = P;    }

            SP += SNOW;
            float melt = fminf(fmaxf(cfmaxdt * (T - TTp), 0.0f), SP);
            MW += melt;  SP -= melt;
            float refr = fminf(fmaxf(cfrcfmaxdt * (TTp - T), 0.0f), MW);
            SP += refr;  MW -= refr;
            float tosoil = fmaxf(MW - CWH * SP, 0.0f);
            MW -= tosoil;

            float win   = RAIN + tosoil;
            float ratio = SM * invFC;
            float sat   = fminf(ratio, 1.0f);                       // SM > 0 always
            float fcap  = f0dt * (FMIN + om_fmin *
                          __powf(fmaxf(1.0f - sat, 1e-6f), ALPHA));
            float infil = fminf(win, fcap);
            float surf  = win - infil;
            float soilw = fminf(__powf(ratio, BETA), 1.0f);
            float rech  = infil * soilw;
            SM += infil - rech;
            float excs  = fmaxf(SM - FC, 0.0f);
            SM -= excs;
            float evap  = fminf(__powf(SM * invLPFC, BETAET), 1.0f);
            float AET   = fminf(SM, PV * evap);
            SM = fmaxf(SM - AET, 1e-5f);
            float cap   = fminf(SLZ, Cc * SLZ * (1.0f - fminf(SM * invFC, 1.0f)));
            SM  += cap;
            SLZ -= cap;
            SUZ += rech + excs + surf;
            float perc = fminf(SUZ, percdt);
            SUZ -= perc;
            SLZ += perc;
            float Q0 = k0dt * fmaxf(SUZ - UZL, 0.0f);
            SUZ -= Q0;
            float Q1 = k1dt * SUZ;
            SUZ -= Q1;
            float Q2 = k2dt * SLZ;
            SLZ -= Q2;

            float Qm = Q0 + Q1 + Q2;
            float other = __shfl_xor_sync(0xffffffffu, Qm, 1);
            if (m == 0)
                g_q[(t0 + u) * NGRID + g] = 0.5f * (Qm + other);
        }
#pragma unroll
        for (int u = 0; u < U; u++) { Pb[u] = Pn[u]; Tb[u] = Tn[u]; Eb[u] = En[u]; }
    }
}

// ---------------------------------------------------------------------------
// Stage 2: gamma routing weights, one thread per grid.
// ---------------------------------------------------------------------------
__global__ void __launch_bounds__(128) weights_kernel(const float* __restrict__ distr)
{
    int g = blockIdx.x * blockDim.x + threadIdx.x;
    if (g >= NGRID) return;

    float aa  = fmaxf(distr[g * 3 + 0] * 5.0f,  0.0f) + 0.1f;
    float th  = fmaxf(distr[g * 3 + 1] * 12.0f, 0.0f) + 0.5f;
    float tau = distr[g * 3 + 2] * 48.0f;

    float lga   = lgammaf(aa);
    float lth   = logf(th);
    float invth = 1.0f / th;
    float am1   = aa - 1.0f;

    float ws[LENF];
    float s = 0.0f;
#pragma unroll
    for (int k = 0; k < LENF; k++) {
        float t  = (float)k + 0.5f;
        float ts = fmaxf(t - tau, 0.001f);
        float lw = -lga - aa * lth + am1 * logf(ts) - ts * invth;
        float w  = expf(lw);
        ws[k] = w;
        s += w;
    }
    float inv = 1.0f / s;
#pragma unroll
    for (int k = 0; k < LENF; k++)
        g_w[k * NGRID + g] = ws[k] * inv;
}

// ---------------------------------------------------------------------------
// Stage 3: 72-tap causal FIR. Tile 32 grids x 64 timesteps per block;
// 8 outputs/thread with a mod-8 register rolling window (2 LDS per 8 FMA).
// ---------------------------------------------------------------------------
#define CONV_GT   32
#define CONV_TT   64
#define CONV_RPT  8

__global__ void __launch_bounds__(256) conv_kernel(float* __restrict__ out)
{
    __shared__ float q_sh[CONV_TT + LENF - 1][CONV_GT];   // 135 x 32
    __shared__ float w_sh[LENF][CONV_GT];                 // 72 x 32

    const int tid   = threadIdx.x;
    const int gbase = blockIdx.x * CONV_GT;
    const int t0    = blockIdx.y * CONV_TT;

    for (int idx = tid; idx < (CONV_TT + LENF - 1) * CONV_GT; idx += 256) {
        int j = idx >> 5, c = idx & 31;
        int tq = t0 - (LENF - 1) + j;
        float v = 0.0f;
        if (tq >= 0 && tq < NSTEPS) v = g_q[tq * NGRID + gbase + c];
        q_sh[j][c] = v;
    }
    for (int idx = tid; idx < LENF * CONV_GT; idx += 256) {
        int k = idx >> 5, c = idx & 31;
        w_sh[k][c] = g_w[k * NGRID + gbase + c];
    }
    __syncthreads();

    const int tx   = tid & 31;
    const int ty   = tid >> 5;        // 0..7
    const int trow = ty * CONV_RPT;

    float acc[CONV_RPT];
#pragma unroll
    for (int r = 0; r < CONV_RPT; r++) acc[r] = 0.0f;

    // buf[i] holds q_sh[row] where row % 8 == i (rows are consecutive)
    float buf[CONV_RPT];
#pragma unroll
    for (int i = 0; i < CONV_RPT; i++)
        buf[(LENF - 1 + i) & 7] = q_sh[trow + LENF - 1 + i][tx];

#pragma unroll
    for (int k = 0; k < LENF; k++) {
        float wv = w_sh[k][tx];
#pragma unroll
        for (int r = 0; r < CONV_RPT; r++)
            acc[r] += wv * buf[(LENF - 1 - k + r) & 7];
        if (k < LENF - 1)
            buf[(LENF - 2 - k) & 7] = q_sh[trow + LENF - 2 - k][tx];
    }

#pragma unroll
    for (int r = 0; r < CONV_RPT; r++) {
        int t = t0 + trow + r;
        if (t < NSTEPS)
            out[t * NGRID + gbase + tx] = acc[r];
    }
}

// ---------------------------------------------------------------------------
extern "C" void kernel_launch(void* const* d_in, const int* in_sizes, int n_in,
                              void* d_out, int out_size)
{
    const float* prcp  = (const float*)d_in[0];
    const float* tmean = (const float*)d_in[1];
    const float* pet   = (const float*)d_in[2];
    const float* phy   = (const float*)d_in[3];
    const float* distr = (const float*)d_in[4];
    float* out = (float*)d_out;

    weights_kernel<<<(NGRID + 127) / 128, 128>>>(distr);
    hbv_scan_kernel<<<(NGRID * NMUL) / 128, 128>>>(prcp, tmean, pet, phy);

    dim3 gc(NGRID / CONV_GT, (NSTEPS + CONV_TT - 1) / CONV_TT);
    conv_kernel<<<gc, 256>>>(out);
}

// round 2
// speedup vs baseline: 1.3173x; 1.3173x over previous
#include <cuda_runtime.h>
#include <math.h>

#define NSTEPS 8760
#define NGRID  2048
#define NMUL   2
#define LENF   72
#define DTC    (1.0f/24.0f)

// Scratch (device globals: no allocation allowed in kernel_launch)
__device__ float g_q2[NSTEPS * NGRID * NMUL];  // per-(t, grid, mul) discharge
__device__ float g_w[LENF * NGRID];            // normalized gamma weights [k][g]

__device__ __forceinline__ float flg2(float x) {
    float y; asm("lg2.approx.f32 %0, %1;" : "=f"(y) : "f"(x)); return y;
}
__device__ __forceinline__ float fex2(float x) {
    float y; asm("ex2.approx.f32 %0, %1;" : "=f"(y) : "f"(x)); return y;
}
__device__ __forceinline__ float fpowa(float x, float p) {  // x > 0
    return fex2(p * flg2(x));
}

// ---------------------------------------------------------------------------
// Stage 1: HBV scan. One thread per (grid, mul); 4096 threads, latency-bound.
// ---------------------------------------------------------------------------
__global__ void __launch_bounds__(128) hbv_scan_kernel(
    const float* __restrict__ prcp,
    const float* __restrict__ tmean,
    const float* __restrict__ pet,
    const float* __restrict__ phy)
{
    const int tid = blockIdx.x * 128 + threadIdx.x;   // 0..4095
    const int g = tid >> 1;
    const int m = tid & 1;

    const float lb[19] = {1.0f, 50.0f, 0.05f, 0.01f, 0.001f, 0.2f, 0.0f, 0.0f,
                          -2.5f, 0.5f, 0.0f, 0.0f, 0.3f, 0.0f, 0.0f, 0.0f,
                          5.0f/DTC, 0.0f, 0.5f};
    const float ub[19] = {6.0f, 1000.0f, 0.9f, 0.5f, 0.2f, 1.0f, 10.0f, 100.0f,
                          2.5f, 10.0f, 0.1f, 0.2f, 5.0f, 1.0f, 20.0f, 2500.0f,
                          120.0f/DTC, 1.0f, 5.0f};
    float pp[19];
#pragma unroll
    for (int i = 0; i < 19; i++) {
        float r = phy[g * (19 * NMUL) + i * NMUL + m];
        pp[i] = lb[i] + r * (ub[i] - lb[i]);
    }
    const float BETA   = pp[0];
    const float FC     = pp[1];
    const float UZL    = pp[7];
    const float TTp    = pp[8];
    const float CWH    = pp[11];
    const float BETAET = pp[12];
    const float Cc     = pp[13];
    const float FMIN   = pp[17];
    const float ALPHA  = pp[18];

    const float invFC       = 1.0f / FC;
    const float k0dt        = pp[2] * DTC;
    const float k1dt        = pp[3] * DTC;
    const float k2dt        = pp[4] * DTC;
    const float percdt      = pp[6] * DTC;
    const float cfmaxdt     = pp[9] * DTC;
    const float cfrcfmaxdt  = pp[10] * cfmaxdt;
    const float f0dt        = pp[16] * DTC;
    const float fmin_f0dt   = FMIN * f0dt;
    const float omfmin_f0dt = (1.0f - FMIN) * f0dt;
    const float invLPFC     = 1.0f / (pp[5] * FC);
    const float evap_c      = BETAET * flg2(invLPFC);   // folded constant

    float SP  = 0.001f, MW = 0.001f, SM = 0.001f, SUZ = 0.001f, SLZ = 0.001f;

    const int U = 8;                                     // 8760 % 8 == 0
    float Pb[U], Tb[U], Eb[U];
#pragma unroll
    for (int u = 0; u < U; u++) {
        Pb[u] = prcp [u * NGRID + g];
        Tb[u] = tmean[u * NGRID + g];
        Eb[u] = pet  [u * NGRID + g];
    }

    // one HBV step (carry by reference; branch-free, chain-compressed)
    auto step = [&](float P, float T, float PV, int t) {
        // snow subsystem (independent of soil; short chain)
        float SNOW = (T < TTp) ? P : 0.0f;
        float RAIN = P - SNOW;
        float SP1  = SP + SNOW;
        float melt = fminf(fmaxf(cfmaxdt * (T - TTp), 0.0f), SP1);
        float MW1  = MW + melt;
        float SP2  = SP1 - melt;
        float refr = fminf(fmaxf(cfrcfmaxdt * (TTp - T), 0.0f), MW1);
        SP = SP2 + refr;
        float MW2    = MW1 - refr;
        float tosoil = fmaxf(fmaf(-CWH, SP, MW2), 0.0f);
        MW = MW2 - tosoil;
        float win = RAIN + tosoil;

        // soil moisture (the critical carry cycle)
        float ratio = SM * invFC;
        float omr   = fmaxf(1.0f - ratio, 1e-6f);        // = max(1-clip(r,0,1),1e-6)
        float fcap  = fmaf(omfmin_f0dt, fpowa(omr, ALPHA), fmin_f0dt);
        float infil = fminf(win, fcap);
        float soilw = fminf(fpowa(ratio, BETA), 1.0f);
        float rech  = infil * soilw;
        float SM1   = fmaf(infil, 1.0f - soilw, SM);     // SM + infil - rech
        float SM2   = fminf(SM1, FC);
        float excs  = SM1 - SM2;
        float evap  = fminf(fex2(fmaf(flg2(SM2), BETAET, evap_c)), 1.0f);
        float AET   = fminf(SM2, PV * evap);
        float SM3   = fmaxf(SM2 - AET, 1e-5f);
        float u3    = fminf(SM3 * invFC, 1.0f);
        float cap   = SLZ * fmaf(-Cc, u3, Cc);           // C*(1-u) in [0,1] since C<=1
        SM = SM3 + cap;

        // upper / lower zones
        float surf = win - infil;
        float SUZ1 = SUZ + (rech + excs) + surf;
        float perc = fminf(SUZ1, percdt);
        float SUZ2 = SUZ1 - perc;
        float Q0   = k0dt * fmaxf(SUZ2 - UZL, 0.0f);
        float SUZ3 = SUZ2 - Q0;
        float Q1   = k1dt * SUZ3;
        SUZ = SUZ3 - Q1;
        float SLZ1 = (SLZ - cap) + perc;
        float Q2   = k2dt * SLZ1;
        SLZ = SLZ1 - Q2;

        g_q2[t * (NGRID * NMUL) + tid] = Q0 + Q1 + Q2;   // coalesced, unconditional
    };

    // main loop: branch-free body, prefetch next U-block
    for (int t0 = 0; t0 < NSTEPS - U; t0 += U) {
        float Pn[U], Tn[U], En[U];
        const int t1 = t0 + U;
#pragma unroll
        for (int u = 0; u < U; u++) {
            Pn[u] = prcp [(t1 + u) * NGRID + g];
            Tn[u] = tmean[(t1 + u) * NGRID + g];
            En[u] = pet  [(t1 + u) * NGRID + g];
        }
#pragma unroll
        for (int u = 0; u < U; u++) step(Pb[u], Tb[u], Eb[u], t0 + u);
#pragma unroll
        for (int u = 0; u < U; u++) { Pb[u] = Pn[u]; Tb[u] = Tn[u]; Eb[u] = En[u]; }
    }
    // peeled last block
#pragma unroll
    for (int u = 0; u < U; u++) step(Pb[u], Tb[u], Eb[u], NSTEPS - U + u);
}

// ---------------------------------------------------------------------------
// Stage 2: gamma routing weights, one thread per grid.
// ---------------------------------------------------------------------------
__global__ void __launch_bounds__(128) weights_kernel(const float* __restrict__ distr)
{
    int g = blockIdx.x * blockDim.x + threadIdx.x;
    if (g >= NGRID) return;

    float aa  = fmaxf(distr[g * 3 + 0] * 5.0f,  0.0f) + 0.1f;
    float th  = fmaxf(distr[g * 3 + 1] * 12.0f, 0.0f) + 0.5f;
    float tau = distr[g * 3 + 2] * 48.0f;

    float lga   = lgammaf(aa);
    float lth   = logf(th);
    float invth = 1.0f / th;
    float am1   = aa - 1.0f;

    float ws[LENF];
    float s = 0.0f;
#pragma unroll
    for (int k = 0; k < LENF; k++) {
        float t  = (float)k + 0.5f;
        float ts = fmaxf(t - tau, 0.001f);
        float lw = -lga - aa * lth + am1 * logf(ts) - ts * invth;
        float w  = expf(lw);
        ws[k] = w;
        s += w;
    }
    float inv = 1.0f / s;
#pragma unroll
    for (int k = 0; k < LENF; k++)
        g_w[k * NGRID + g] = ws[k] * inv;
}

// ---------------------------------------------------------------------------
// Stage 3: 72-tap causal FIR; mul-pair averaged at load via float2.
// ---------------------------------------------------------------------------
#define CONV_GT   32
#define CONV_TT   64
#define CONV_RPT  8

__global__ void __launch_bounds__(256) conv_kernel(float* __restrict__ out)
{
    __shared__ float q_sh[CONV_TT + LENF - 1][CONV_GT];   // 135 x 32
    __shared__ float w_sh[LENF][CONV_GT];                 // 72 x 32

    const int tid   = threadIdx.x;
    const int gbase = blockIdx.x * CONV_GT;
    const int t0    = blockIdx.y * CONV_TT;

    const float2* q2 = reinterpret_cast<const float2*>(g_q2);

    for (int idx = tid; idx < (CONV_TT + LENF - 1) * CONV_GT; idx += 256) {
        int j = idx >> 5, c = idx & 31;
        int tq = t0 - (LENF - 1) + j;
        float v = 0.0f;
        if (tq >= 0 && tq < NSTEPS) {
            float2 p = q2[tq * NGRID + gbase + c];
            v = 0.5f * (p.x + p.y);
        }
        q_sh[j][c] = v;
    }
    for (int idx = tid; idx < LENF * CONV_GT; idx += 256) {
        int k = idx >> 5, c = idx & 31;
        w_sh[k][c] = g_w[k * NGRID + gbase + c];
    }
    __syncthreads();

    const int tx   = tid & 31;
    const int ty   = tid >> 5;        // 0..7
    const int trow = ty * CONV_RPT;

    float acc[CONV_RPT];
#pragma unroll
    for (int r = 0; r < CONV_RPT; r++) acc[r] = 0.0f;

    float buf[CONV_RPT];              // rolling window, mod-8 register ring
#pragma unroll
    for (int i = 0; i < CONV_RPT; i++)
        buf[(LENF - 1 + i) & 7] = q_sh[trow + LENF - 1 + i][tx];

#pragma unroll
    for (int k = 0; k < LENF; k++) {
        float wv = w_sh[k][tx];
#pragma unroll
        for (int r = 0; r < CONV_RPT; r++)
            acc[r] += wv * buf[(LENF - 1 - k + r) & 7];
        if (k < LENF - 1)
            buf[(LENF - 2 - k) & 7] = q_sh[trow + LENF - 2 - k][tx];
    }

#pragma unroll
    for (int r = 0; r < CONV_RPT; r++) {
        int t = t0 + trow + r;
        if (t < NSTEPS)
            out[t * NGRID + gbase + tx] = acc[r];
    }
}

// ---------------------------------------------------------------------------
extern "C" void kernel_launch(void* const* d_in, const int* in_sizes, int n_in,
                              void* d_out, int out_size)
{
    const float* prcp  = (const float*)d_in[0];
    const float* tmean = (const float*)d_in[1];
    const float* pet   = (const float*)d_in[2];
    const float* phy   = (const float*)d_in[3];
    const float* distr = (const float*)d_in[4];
    float* out = (float*)d_out;

    hbv_scan_kernel<<<(NGRID * NMUL) / 128, 128>>>(prcp, tmean, pet, phy);
    weights_kernel<<<(NGRID + 127) / 128, 128>>>(distr);

    dim3 gc(NGRID / CONV_GT, (NSTEPS + CONV_TT - 1) / CONV_TT);
    conv_kernel<<<gc, 256>>>(out);
}